// round 6
// baseline (speedup 1.0000x reference)
#include <cuda_runtime.h>
#include <float.h>

// Fused MaxPool(2x2,s1,SAME) -> depthwise 3x3 binomial blur -> AvgPool(2x2,s2)
// == separable 4x4 stencil w=(1,3,3,1)/8 stride 2 over maxpool output y.
//
// R6: R3's proven pipeline shape (double-buffered column PAIRS, 14-load
// bursts, full compute block between issue and consume) but with scalar
// float lanes: warp = 32 channels, 4 channel-quarter warps per strip.
// Halves per-thread state -> ~70 regs -> 6-8 CTAs/SM at unchanged burst MLP.
// Boundary handling: clamped addresses at issue, value fixups at consume.

#define NROWP  28
#define ROWSTR (112*128)    // floats per x row
#define PXSTR  128          // floats per pixel

// Load 7 clamped rows of column xc0+T into dst. Addresses always in-bounds;
// out-of-range VALUES are neutralized at consume time.
#define LOADCOL(dst, T) do {                                              \
    int _cc = xc0 + (T);                                                  \
    _cc = _cc < 0 ? 0 : (_cc > 111 ? 111 : _cc);                          \
    const float* _p = base + (size_t)_cc * PXSTR;                         \
    dst[0] = __ldg(_p + rowOff[0]);                                       \
    dst[1] = __ldg(_p + rowOff[1]);                                       \
    dst[2] = __ldg(_p + rowOff[2]);                                       \
    dst[3] = __ldg(_p + rowOff[3]);                                       \
    dst[4] = __ldg(_p + rowOff[4]);                                       \
    dst[5] = __ldg(_p + rowOff[5]);                                       \
    dst[6] = __ldg(_p + rowOff[6]);                                       \
} while (0)

// Finalize y column ty (literal): vertical (1,3,3,1)/8 then horizontal
// scatter into the 2-slot accumulator ring.
#define STEP(prevcm, curcm, TY) do {                                      \
    const bool _skip = ((TY)==0 && leftSkip) || ((TY)==29 && rightSkip);  \
    if (!_skip) {                                                         \
        float yc[6];                                                      \
        _Pragma("unroll")                                                 \
        for (int _k = 0; _k < 6; _k++)                                    \
            yc[_k] = fmaxf(prevcm[_k], curcm[_k]);                        \
        if (!okTop) yc[0] = 0.f;                                          \
        if (!okBot) yc[5] = 0.f;                                          \
        const int   _m  = (TY) >> 1;                                      \
        const float _wA = ((TY) & 1) ? wv1 : wv0;                         \
        const float _wB = ((TY) & 1) ? wv0 : wv1;                         \
        _Pragma("unroll")                                                 \
        for (int _rl = 0; _rl < 2; _rl++) {                               \
            float V;                                                      \
            V = wv0 * yc[2*_rl + 0];                                      \
            V = fmaf(wv1, yc[2*_rl + 1], V);                              \
            V = fmaf(wv1, yc[2*_rl + 2], V);                              \
            V = fmaf(wv0, yc[2*_rl + 3], V);                              \
            if (_m < 14) acc[_rl][_m & 1] = fmaf(_wA, V, acc[_rl][_m & 1]); \
            if (_m >= 1) acc[_rl][(_m & 1) ^ 1] =                         \
                fmaf(_wB, V, acc[_rl][(_m & 1) ^ 1]);                     \
        }                                                                 \
    }                                                                     \
} while (0)

// Column pair-maxes with bottom-row fixup (row xr0+5 == x row 112 -> -inf).
#define MAKECM(cm, xv) do {                                               \
    const float _x5 = okBot ? xv[5] : -FLT_MAX;                           \
    cm[0] = fmaxf(xv[0], xv[1]);                                          \
    cm[1] = fmaxf(xv[1], xv[2]);                                          \
    cm[2] = fmaxf(xv[2], xv[3]);                                          \
    cm[3] = fmaxf(xv[3], xv[4]);                                          \
    cm[4] = fmaxf(xv[4], _x5);                                            \
    cm[5] = fmaxf(_x5,   xv[6]);                                          \
} while (0)

__global__ void __launch_bounds__(128, 6)
mbp_kernel(const float* __restrict__ x, float* __restrict__ out) {
    const int lane = threadIdx.x;
    const int wid  = blockIdx.x * 4 + threadIdx.y;   // 14336 warp tasks
    const int chQ  = wid & 3;                        // channel quarter
    const int strip = wid >> 2;                      // 3584 strips
    const int cj = strip & 3;                        // 4 col chunks of 14
    const int s2 = strip >> 2;
    const int ti = s2 % NROWP;                       // 28 row pairs
    const int b  = s2 / NROWP;

    const int oi0 = 2 * ti;
    const int oj0 = 14 * cj;
    const int xr0 = 4 * ti - 1;                      // first x row
    const int xc0 = 28 * cj - 1;                     // first x col

    const bool okTop     = (ti != 0);
    const bool okBot     = (ti != NROWP - 1);
    const bool leftSkip  = (cj == 0);
    const bool rightSkip = (cj == 3);

    const float wv0 = 0.125f, wv1 = 0.375f;          // (1,3,3,1)/8

    const float* base = x + (size_t)b * 112 * ROWSTR + chQ * 32 + lane;

    // Clamped row offsets (element units). Row xr0 (-1 at top) and rows
    // xr0+5/6 (112/113 at bottom) clamp; their values only reach zeroed /
    // NEG-substituted lanes.
    int rowOff[7];
#pragma unroll
    for (int k = 0; k < 7; k++) {
        int gr = xr0 + k;
        gr = gr < 0 ? 0 : (gr > 111 ? 111 : gr);
        rowOff[k] = gr * ROWSTR;
    }

    float* ob = out + ((size_t)(b * 56 + oi0) * 56 + oj0) * 128
                    + chQ * 32 + lane;

    // Prime: column xc0 -> cmPrev
    float cmPrev[6];
    {
        float xv[7];
        LOADCOL(xv, 0);
        MAKECM(cmPrev, xv);
    }

    float acc[2][2] = {{0.f, 0.f}, {0.f, 0.f}};      // [row][col&1] ring

    // Double-buffered column pairs; buffer i&1 holds columns of iteration i.
    float xa[2][7], xb2[2][7];
    LOADCOL(xa[0],  1);
    LOADCOL(xb2[0], 2);

#pragma unroll
    for (int i = 0; i < 15; i++) {
        const int cur = i & 1, nxt = cur ^ 1;
        if (i < 14) {                                // 14-load burst for i+1
            LOADCOL(xa[nxt],  3 + 2*i);
            LOADCOL(xb2[nxt], 4 + 2*i);
        }

        float cmA[6], cmB[6];
        MAKECM(cmA, xa[cur]);
        MAKECM(cmB, xb2[cur]);

        // Right edge: iteration 14's xa column is x col 112 -> -inf pad.
        if (i == 14 && rightSkip) {
#pragma unroll
            for (int k = 0; k < 6; k++) cmA[k] = -FLT_MAX;
        }

        STEP(cmPrev, cmA, 2*i);                      // y col ty = 2i
        STEP(cmA,    cmB, 2*i + 1);                  // y col ty = 2i+1

        if (i >= 1) {                                // out col i-1 complete
            const int wl = i - 1, s = wl & 1;
#pragma unroll
            for (int rl = 0; rl < 2; rl++) {
                ob[((size_t)rl * 56 + wl) * 128] = acc[rl][s];
                acc[rl][s] = 0.f;
            }
        }

#pragma unroll
        for (int k = 0; k < 6; k++) cmPrev[k] = cmB[k];
    }
}

extern "C" void kernel_launch(void* const* d_in, const int* in_sizes, int n_in,
                              void* d_out, int out_size) {
    const float* x = (const float*)d_in[0];     // (32,112,112,128) f32
    // d_in[1] = blur kernel, baked into (1,3,3,1)/8
    float* out = (float*)d_out;                 // (32,56,56,128) f32

    // 3584 strips x 4 channel quarters = 14336 warp tasks, 4 warps/CTA
    dim3 block(32, 4);
    dim3 grid(14336 / 4);                       // 3584 blocks
    mbp_kernel<<<grid, block>>>(x, out);
}

// round 7
// speedup vs baseline: 1.4006x; 1.4006x over previous
#include <cuda_runtime.h>
#include <float.h>

// Fused MaxPool(2x2,s1,SAME) -> depthwise 3x3 binomial blur -> AvgPool(2x2,s2)
// == separable 4x4 stencil w=(1,3,3,1)/8 stride 2 over maxpool output y.
//
// R7: R3's float2 pair-burst pipeline, deepened to a 3-slot ring of column
// PAIRS (prefetch distance 2): 42 loads = 10.75KB in flight per warp,
// 3 CTAs/SM -> ~129KB/SM outstanding. Clamped-offset boundary handling.

#define NROWP  28
#define ROWSTR (112*64)     // float2 per x row
#define PXSTR  64           // float2 per pixel

__device__ __forceinline__ float2 f2max(float2 a, float2 b) {
    return make_float2(fmaxf(a.x,b.x), fmaxf(a.y,b.y));
}
__device__ __forceinline__ void f2fma(float2& a, float w, float2 v) {
    a.x = fmaf(w, v.x, a.x); a.y = fmaf(w, v.y, a.y);
}

// Load 7 clamped rows of column xc0+T. Addresses always in-bounds;
// out-of-range VALUES are neutralized at consume time (see MAKECM / STEP).
#define LOADCOL(dst, T) do {                                              \
    int _cc = xc0 + (T);                                                  \
    _cc = _cc < 0 ? 0 : (_cc > 111 ? 111 : _cc);                          \
    const float2* _p = base + (size_t)_cc * PXSTR;                        \
    dst[0] = __ldg(_p + rowOff[0]);                                       \
    dst[1] = __ldg(_p + rowOff[1]);                                       \
    dst[2] = __ldg(_p + rowOff[2]);                                       \
    dst[3] = __ldg(_p + rowOff[3]);                                       \
    dst[4] = __ldg(_p + rowOff[4]);                                       \
    dst[5] = __ldg(_p + rowOff[5]);                                       \
    dst[6] = __ldg(_p + rowOff[6]);                                       \
} while (0)

// Column pair-maxes; bottom strip's x row 112 (xv[5]) is -inf SAME padding.
#define MAKECM(cm, xv) do {                                               \
    const float2 _x5 = okBot ? xv[5] : NEG;                               \
    cm[0] = f2max(xv[0], xv[1]);                                          \
    cm[1] = f2max(xv[1], xv[2]);                                          \
    cm[2] = f2max(xv[2], xv[3]);                                          \
    cm[3] = f2max(xv[3], xv[4]);                                          \
    cm[4] = f2max(xv[4], _x5);                                            \
    cm[5] = f2max(_x5,   xv[6]);                                          \
} while (0)

// Finalize y column ty (literal after unroll): vertical (1,3,3,1)/8 then
// scatter into the 2-slot per-row accumulator ring.
#define STEP(prevcm, curcm, TY) do {                                      \
    const bool _skip = ((TY)==0 && leftSkip) || ((TY)==29 && rightSkip);  \
    if (!_skip) {                                                         \
        float2 yc[6];                                                     \
        _Pragma("unroll")                                                 \
        for (int _k = 0; _k < 6; _k++)                                    \
            yc[_k] = f2max(prevcm[_k], curcm[_k]);                        \
        if (!okTop) yc[0] = ZERO;                                         \
        if (!okBot) yc[5] = ZERO;                                         \
        const int   _m  = (TY) >> 1;                                      \
        const float _wA = ((TY) & 1) ? wv1 : wv0;                         \
        const float _wB = ((TY) & 1) ? wv0 : wv1;                         \
        _Pragma("unroll")                                                 \
        for (int _rl = 0; _rl < 2; _rl++) {                               \
            float2 V = ZERO;                                              \
            f2fma(V, wv0, yc[2*_rl + 0]);                                 \
            f2fma(V, wv1, yc[2*_rl + 1]);                                 \
            f2fma(V, wv1, yc[2*_rl + 2]);                                 \
            f2fma(V, wv0, yc[2*_rl + 3]);                                 \
            if (_m < 14) f2fma(acc[_rl][_m & 1], _wA, V);                 \
            if (_m >= 1) f2fma(acc[_rl][(_m & 1) ^ 1], _wB, V);           \
        }                                                                 \
    }                                                                     \
} while (0)

__global__ void __launch_bounds__(128, 3)
mbp_kernel(const float2* __restrict__ x, float2* __restrict__ out) {
    const int lane   = threadIdx.x;
    const int wid    = blockIdx.x * 4 + threadIdx.y;   // 7168 warp tasks
    const int chHalf = wid & 1;
    const int strip  = wid >> 1;                       // 3584 strips
    const int cj = strip & 3;                          // 4 col chunks of 14
    const int s2 = strip >> 2;
    const int ti = s2 % NROWP;                         // 28 row pairs
    const int b  = s2 / NROWP;

    const int oi0 = 2 * ti;
    const int oj0 = 14 * cj;
    const int xr0 = 4 * ti - 1;                        // first x row
    const int xc0 = 28 * cj - 1;                       // first x col

    const bool okTop     = (ti != 0);
    const bool okBot     = (ti != NROWP - 1);
    const bool leftSkip  = (cj == 0);
    const bool rightSkip = (cj == 3);

    const float2 NEG  = make_float2(-FLT_MAX, -FLT_MAX);
    const float2 ZERO = make_float2(0.f, 0.f);
    const float wv0 = 0.125f, wv1 = 0.375f;            // (1,3,3,1)/8

    const float2* base = x + (size_t)b * 112 * ROWSTR + chHalf * 32 + lane;

    // Clamped row offsets (float2 units). Row -1 (top) and rows 112/113
    // (bottom) clamp; their values only reach zeroed / NEG-substituted lanes.
    int rowOff[7];
#pragma unroll
    for (int k = 0; k < 7; k++) {
        int gr = xr0 + k;
        gr = gr < 0 ? 0 : (gr > 111 ? 111 : gr);
        rowOff[k] = gr * ROWSTR;
    }

    float2* ob = out + ((size_t)(b * 56 + oi0) * 56 + oj0) * 64
                     + chHalf * 32 + lane;

    // 3-slot ring of column pairs; slot i%3 holds iteration i's pair.
    float2 xbuf[3][2][7];

    // Prologue burst: prime column + 3 pairs = 49 loads front-batched.
    float2 cmPrev[6];
    {
        float2 xv[7];
        LOADCOL(xv, 0);
        LOADCOL(xbuf[0][0], 1); LOADCOL(xbuf[0][1], 2);   // pair 0
        LOADCOL(xbuf[1][0], 3); LOADCOL(xbuf[1][1], 4);   // pair 1
        LOADCOL(xbuf[2][0], 5); LOADCOL(xbuf[2][1], 6);   // pair 2
        MAKECM(cmPrev, xv);
    }

    float2 acc[2][2];                                  // [row][col&1] ring
    acc[0][0]=ZERO; acc[0][1]=ZERO; acc[1][0]=ZERO; acc[1][1]=ZERO;

#pragma unroll
    for (int i = 0; i < 15; i++) {
        const int cur = i % 3;

        // Consume pair i (loaded 3 compute blocks ago).
        float2 cmA[6], cmB[6];
        MAKECM(cmA, xbuf[cur][0]);
        MAKECM(cmB, xbuf[cur][1]);

        // Slot freed -> refill with pair i+3 (cols 7+2i, 8+2i).
        if (i + 3 <= 14) {
            LOADCOL(xbuf[cur][0], 7 + 2*i);
            LOADCOL(xbuf[cur][1], 8 + 2*i);
        }

        // Right edge: iteration 14's first column is x col 112 -> -inf pad.
        if (i == 14 && rightSkip) {
#pragma unroll
            for (int k = 0; k < 6; k++) cmA[k] = NEG;
        }

        STEP(cmPrev, cmA, 2*i);                        // y col ty = 2i
        STEP(cmA,    cmB, 2*i + 1);                    // y col ty = 2i+1

        if (i >= 1) {                                  // out col i-1 complete
            const int wl = i - 1, s = wl & 1;
#pragma unroll
            for (int rl = 0; rl < 2; rl++) {
                ob[((size_t)rl * 56 + wl) * 64] = acc[rl][s];
                acc[rl][s] = ZERO;
            }
        }

#pragma unroll
        for (int k = 0; k < 6; k++) cmPrev[k] = cmB[k];
    }
}

extern "C" void kernel_launch(void* const* d_in, const int* in_sizes, int n_in,
                              void* d_out, int out_size) {
    const float2* x = (const float2*)d_in[0];   // (32,112,112,128) f32
    // d_in[1] = blur kernel, baked into (1,3,3,1)/8
    float2* out = (float2*)d_out;               // (32,56,56,128) f32

    // 3584 strips x 2 channel halves = 7168 warp tasks, 4 warps/CTA
    dim3 block(32, 4);
    dim3 grid(7168 / 4);                        // 1792 blocks
    mbp_kernel<<<grid, block>>>(x, out);
}